// round 11
// baseline (speedup 1.0000x reference)
#include <cuda_runtime.h>
#include <cuda_bf16.h>
#include <math.h>

// Problem constants
#define BB 8
#define CC 32          // input channels
#define CA 33          // augmented channels (density + 32)
#define WW 256
#define HH 128
#define XX 720
#define YY 361

typedef unsigned long long ull;

// Scratch (device globals: allocation-free)
__device__ float g_w0[BB * WW * XX];              // [b][w][x]
__device__ float g_w1[BB * HH * YY];              // [b][h][y]
__device__ float g_U [(size_t)BB * CA * XX * HH]; // [b][c][x][h]

// ---------------- packed f32x2 helpers ----------------
__device__ __forceinline__ ull pack2(float v) {
    ull r;
    unsigned u = __float_as_uint(v);
    asm("mov.b64 %0, {%1, %1};" : "=l"(r) : "r"(u));
    return r;
}
__device__ __forceinline__ void fma2(ull& d, ull a, ull b) {
    asm("fma.rn.f32x2 %0, %1, %2, %0;" : "+l"(d) : "l"(a), "l"(b));
}
__device__ __forceinline__ float2 unpack2(ull v) {
    unsigned lo, hi;
    asm("mov.b64 {%0, %1}, %2;" : "=r"(lo), "=r"(hi) : "l"(v));
    return make_float2(__uint_as_float(lo), __uint_as_float(hi));
}

// ---------------------------------------------------------------------------
// Kernel 1: RBF weight matrices.  w = exp(-0.5*(xi-xo)^2 / ls^2)
// ---------------------------------------------------------------------------
__global__ void rbf_all_kernel(const float* __restrict__ inlon,
                               const float* __restrict__ outlon,
                               const float* __restrict__ inlat,
                               const float* __restrict__ outlat,
                               const float* __restrict__ ls) {
    const int N0 = BB * WW * XX;
    const int N1 = BB * HH * YY;
    int idx = blockIdx.x * blockDim.x + threadIdx.x;
    float l = ls[0];
    float inv = 0.5f / (l * l);
    if (idx < N0) {
        int m = idx % XX;
        int r = idx / XX;
        int n = r % WW;
        int b = r / WW;
        float d = inlon[b * WW + n] - outlon[b * XX + m];
        g_w0[idx] = expf(-d * d * inv);
    } else {
        int i2 = idx - N0;
        if (i2 < N1) {
            int m = i2 % YY;
            int r = i2 / YY;
            int n = r % HH;
            int b = r / HH;
            float d = inlat[b * HH + n] - outlat[b * YY + m];
            g_w1[i2] = expf(-d * d * inv);
        }
    }
}

// ---------------------------------------------------------------------------
// Kernel 2: U[b,c,x,h] = sum_w w0[b,w,x] * wt_aug[b,c,w,h]
//   per (b,c): M=720 (x), N=128 (h), K=256 (w)
//   128x128 block tile (M-padded), 256 threads, 8x8 micro (split halves),
//   f32x2 packed accumulation along h. NaN/density handling fused in B load.
//   grid = (6, 1, 264)
// ---------------------------------------------------------------------------
__global__ __launch_bounds__(256, 2) void u_gemm_kernel(const float* __restrict__ wt) {
    __shared__ __align__(16) float As[16][128];   // [k][x]
    __shared__ __align__(16) float Bs[16][128];   // [k][h]

    const int bc = blockIdx.z;
    const int b  = bc / CA;
    const int c  = bc % CA;
    const int x0 = blockIdx.x * 128;
    const int tid = threadIdx.x;
    const int tx = tid & 15;       // -> h quad
    const int ty = tid >> 4;       // -> x quad

    const float* w0b = g_w0 + (size_t)b * WW * XX;
    const int cin = (c == 0) ? 0 : (c - 1);
    const float* wtb = wt + ((size_t)b * CC + cin) * WW * HH;
    const bool dens = (c == 0);

    ull acc[8][4];
#pragma unroll
    for (int i = 0; i < 8; i++)
#pragma unroll
        for (int j = 0; j < 4; j++) acc[i][j] = 0ull;

    const int lr = tid >> 4;         // load row 0..15
    const int lc = (tid & 15) * 8;   // load col 0..120

    for (int k0 = 0; k0 < WW; k0 += 16) {
        // As <- w0[b][k][x0 + lc .. +7]
        {
            const float* src = w0b + (size_t)(k0 + lr) * XX + x0 + lc;
            if (x0 + lc + 7 < XX) {
                *(float4*)&As[lr][lc]     = *(const float4*)src;
                *(float4*)&As[lr][lc + 4] = *(const float4*)(src + 4);
            } else {
#pragma unroll
                for (int e = 0; e < 8; e++)
                    As[lr][lc + e] = (x0 + lc + e < XX) ? src[e] : 0.0f;
            }
        }
        // Bs <- wt_aug[b][c][k][lc .. +7]  (HH == 128 exactly)
        {
            const float* src = wtb + (size_t)(k0 + lr) * HH + lc;
            float4 v0 = *(const float4*)src;
            float4 v1 = *(const float4*)(src + 4);
            float e0[8] = {v0.x, v0.y, v0.z, v0.w, v1.x, v1.y, v1.z, v1.w};
#pragma unroll
            for (int e = 0; e < 8; e++) {
                float v = e0[e];
                v = isnan(v) ? 0.0f : (dens ? 1.0f : v);
                Bs[lr][lc + e] = v;
            }
        }
        __syncthreads();

#pragma unroll
        for (int kk = 0; kk < 16; kk++) {
            float4 a0 = *(const float4*)&As[kk][ty * 4];
            float4 a1 = *(const float4*)&As[kk][64 + ty * 4];
            ulonglong2 b0 = *(const ulonglong2*)&Bs[kk][tx * 4];
            ulonglong2 b1 = *(const ulonglong2*)&Bs[kk][64 + tx * 4];
            ull A2[8];
            A2[0] = pack2(a0.x); A2[1] = pack2(a0.y);
            A2[2] = pack2(a0.z); A2[3] = pack2(a0.w);
            A2[4] = pack2(a1.x); A2[5] = pack2(a1.y);
            A2[6] = pack2(a1.z); A2[7] = pack2(a1.w);
            ull Bp[4] = {b0.x, b0.y, b1.x, b1.y};
#pragma unroll
            for (int i = 0; i < 8; i++)
#pragma unroll
                for (int jp = 0; jp < 4; jp++)
                    fma2(acc[i][jp], A2[i], Bp[jp]);
        }
        __syncthreads();
    }

    float* Ub = g_U + (size_t)bc * XX * HH;
#pragma unroll
    for (int i = 0; i < 8; i++) {
        int x = x0 + ((i < 4) ? (ty * 4 + i) : (64 + ty * 4 + (i - 4)));
        if (x < XX) {
            float2 p0 = unpack2(acc[i][0]);
            float2 p1 = unpack2(acc[i][1]);
            float2 p2 = unpack2(acc[i][2]);
            float2 p3 = unpack2(acc[i][3]);
            *(float4*)&Ub[(size_t)x * HH + tx * 4]      = make_float4(p0.x, p0.y, p1.x, p1.y);
            *(float4*)&Ub[(size_t)x * HH + 64 + tx * 4] = make_float4(p2.x, p2.y, p3.x, p3.y);
        }
    }
}

// ---------------------------------------------------------------------------
// Kernel 3: out[b,c,x,y] = (sum_h U[b,c,x,h] * w1[b,h,y]) [/ clip(density)]
//   per block: (b, 128 x-tile, 128 y-tile); w1 strip 128x128 persistent in
//   dynamic smem; loop over 33 channels, density reciprocal kept in regs.
//   grid = (6, 3, 8), 256 threads, 8x8 micro (split halves), f32x2.
// ---------------------------------------------------------------------------
__global__ __launch_bounds__(256, 1) void out_gemm_kernel(float* __restrict__ out) {
    extern __shared__ __align__(16) float w1s[];   // [128][128]
    __shared__ __align__(16) float As3[16][128];   // [k][x]

    const int b  = blockIdx.z;
    const int x0 = blockIdx.x * 128;
    const int y0 = blockIdx.y * 128;
    const int tid = threadIdx.x;
    const int tx = tid & 15;       // -> y quad
    const int ty = tid >> 4;       // -> x quad

    // Persistent w1 strip: 128 x 128 (y zero-padded past YY)
    const float* w1b = g_w1 + (size_t)b * HH * YY;
#pragma unroll 4
    for (int p = 0; p < 64; p++) {
        int e = p * 256 + tid;
        int k = e >> 7;
        int yy = e & 127;
        int y = y0 + yy;
        w1s[k * 128 + yy] = (y < YY) ? w1b[(size_t)k * YY + y] : 0.0f;
    }
    __syncthreads();

    const int xxL = tid >> 1;          // 0..127
    const int kbL = (tid & 1) * 8;     // 0 or 8

    float rden[8][8];                  // reciprocal of clamped density

    for (int c = 0; c < CA; c++) {
        ull acc[8][4];
#pragma unroll
        for (int i = 0; i < 8; i++)
#pragma unroll
            for (int j = 0; j < 4; j++) acc[i][j] = 0ull;

        const float* Uc = g_U + ((size_t)b * CA + c) * XX * HH;

        for (int k0 = 0; k0 < HH; k0 += 16) {
            // Load As3[k][x] from U[x][k] (k contiguous in U)
            int x = x0 + xxL;
            if (x > XX - 1) x = XX - 1;   // clamp; stores are guarded
            float4 v0 = *(const float4*)&Uc[(size_t)x * HH + k0 + kbL];
            float4 v1 = *(const float4*)&Uc[(size_t)x * HH + k0 + kbL + 4];
            As3[kbL + 0][xxL] = v0.x;
            As3[kbL + 1][xxL] = v0.y;
            As3[kbL + 2][xxL] = v0.z;
            As3[kbL + 3][xxL] = v0.w;
            As3[kbL + 4][xxL] = v1.x;
            As3[kbL + 5][xxL] = v1.y;
            As3[kbL + 6][xxL] = v1.z;
            As3[kbL + 7][xxL] = v1.w;
            __syncthreads();

#pragma unroll
            for (int kk = 0; kk < 16; kk++) {
                float4 a0 = *(const float4*)&As3[kk][ty * 4];
                float4 a1 = *(const float4*)&As3[kk][64 + ty * 4];
                const float* brow = &w1s[(k0 + kk) * 128];
                ulonglong2 b0 = *(const ulonglong2*)&brow[tx * 4];
                ulonglong2 b1 = *(const ulonglong2*)&brow[64 + tx * 4];
                ull A2[8];
                A2[0] = pack2(a0.x); A2[1] = pack2(a0.y);
                A2[2] = pack2(a0.z); A2[3] = pack2(a0.w);
                A2[4] = pack2(a1.x); A2[5] = pack2(a1.y);
                A2[6] = pack2(a1.z); A2[7] = pack2(a1.w);
                ull Bp[4] = {b0.x, b0.y, b1.x, b1.y};
#pragma unroll
                for (int i = 0; i < 8; i++)
#pragma unroll
                    for (int jp = 0; jp < 4; jp++)
                        fma2(acc[i][jp], A2[i], Bp[jp]);
            }
            __syncthreads();
        }

        // Epilogue: c==0 writes density + caches reciprocal; others divide.
        float* outc = out + ((size_t)b * CA + c) * XX * YY;
#pragma unroll
        for (int i = 0; i < 8; i++) {
            int x = x0 + ((i < 4) ? (ty * 4 + i) : (64 + ty * 4 + (i - 4)));
            float2 p0 = unpack2(acc[i][0]);
            float2 p1 = unpack2(acc[i][1]);
            float2 p2 = unpack2(acc[i][2]);
            float2 p3 = unpack2(acc[i][3]);
            float vv[8] = {p0.x, p0.y, p1.x, p1.y, p2.x, p2.y, p3.x, p3.y};
#pragma unroll
            for (int jj = 0; jj < 8; jj++) {
                int y = y0 + ((jj < 4) ? (tx * 4 + jj) : (64 + tx * 4 + (jj - 4)));
                if (c == 0) {
                    float d = fminf(fmaxf(vv[jj], 1e-6f), 100000.0f);
                    rden[i][jj] = 1.0f / d;
                    if (x < XX && y < YY) outc[(size_t)x * YY + y] = vv[jj];
                } else {
                    if (x < XX && y < YY)
                        outc[(size_t)x * YY + y] = vv[jj] * rden[i][jj];
                }
            }
        }
    }
}

// ---------------------------------------------------------------------------
extern "C" void kernel_launch(void* const* d_in, const int* in_sizes, int n_in,
                              void* d_out, int out_size) {
    const float* wt      = (const float*)d_in[0];  // (8,32,256,128)
    const float* xinlon  = (const float*)d_in[1];  // (8,256)
    const float* xinlat  = (const float*)d_in[2];  // (8,128)
    const float* xoutlon = (const float*)d_in[3];  // (8,720)
    const float* xoutlat = (const float*)d_in[4];  // (8,361)
    const float* ls      = (const float*)d_in[5];  // (1,)
    float* out = (float*)d_out;                    // (8,33,720,361)

    // 1) RBF matrices
    {
        int total = BB * WW * XX + BB * HH * YY;
        int blocks = (total + 255) / 256;
        rbf_all_kernel<<<blocks, 256>>>(xinlon, xoutlon, xinlat, xoutlat, ls);
    }
    // 2) U = w0^T @ wt_aug   (contract over W)
    {
        dim3 grid((XX + 127) / 128, 1, BB * CA);   // (6, 1, 264)
        u_gemm_kernel<<<grid, 256>>>(wt);
    }
    // 3) out = U @ w1, fused density normalization (64 KB dynamic smem)
    {
        cudaFuncSetAttribute(out_gemm_kernel,
                             cudaFuncAttributeMaxDynamicSharedMemorySize,
                             128 * 128 * sizeof(float));
        dim3 grid((XX + 127) / 128, (YY + 127) / 128, BB);  // (6, 3, 8)
        out_gemm_kernel<<<grid, 256, 128 * 128 * sizeof(float)>>>(out);
    }
}

// round 12
// speedup vs baseline: 1.0014x; 1.0014x over previous
#include <cuda_runtime.h>
#include <cuda_bf16.h>
#include <math.h>

// Problem constants
#define BB 8
#define CC 32          // input channels
#define CA 33          // augmented channels (density + 32)
#define WW 256
#define HH 128
#define XX 720
#define YY 361

typedef unsigned long long ull;

// Scratch (device globals: allocation-free)
__device__ float g_w0[BB * WW * XX];              // [b][w][x]
__device__ float g_w1[BB * HH * YY];              // [b][h][y]
__device__ float g_U [(size_t)BB * CA * XX * HH]; // [b][c][x][h]

// ---------------- packed f32x2 helpers ----------------
__device__ __forceinline__ ull pack2(float v) {
    ull r;
    unsigned u = __float_as_uint(v);
    asm("mov.b64 %0, {%1, %1};" : "=l"(r) : "r"(u));
    return r;
}
__device__ __forceinline__ void fma2(ull& d, ull a, ull b) {
    asm("fma.rn.f32x2 %0, %1, %2, %0;" : "+l"(d) : "l"(a), "l"(b));
}
__device__ __forceinline__ float2 unpack2(ull v) {
    unsigned lo, hi;
    asm("mov.b64 {%0, %1}, %2;" : "=r"(lo), "=r"(hi) : "l"(v));
    return make_float2(__uint_as_float(lo), __uint_as_float(hi));
}

// ---------------------------------------------------------------------------
// Kernel 1: RBF weight matrices.  w = exp(-0.5*(xi-xo)^2 / ls^2)
// ---------------------------------------------------------------------------
__global__ void rbf_all_kernel(const float* __restrict__ inlon,
                               const float* __restrict__ outlon,
                               const float* __restrict__ inlat,
                               const float* __restrict__ outlat,
                               const float* __restrict__ ls) {
    const int N0 = BB * WW * XX;
    const int N1 = BB * HH * YY;
    int idx = blockIdx.x * blockDim.x + threadIdx.x;
    float l = ls[0];
    float inv = 0.5f / (l * l);
    if (idx < N0) {
        int m = idx % XX;
        int r = idx / XX;
        int n = r % WW;
        int b = r / WW;
        float d = inlon[b * WW + n] - outlon[b * XX + m];
        g_w0[idx] = expf(-d * d * inv);
    } else {
        int i2 = idx - N0;
        if (i2 < N1) {
            int m = i2 % YY;
            int r = i2 / YY;
            int n = r % HH;
            int b = r / HH;
            float d = inlat[b * HH + n] - outlat[b * YY + m];
            g_w1[i2] = expf(-d * d * inv);
        }
    }
}

// ---------------------------------------------------------------------------
// Kernel 2: U[b,c,x,h] = sum_w w0[b,w,x] * wt_aug[b,c,w,h]
//   per (b,c): M=720 (x), N=128 (h), K=256 (w)
//   128x128 block tile (M-padded), 256 threads, 8x8 micro (split halves),
//   f32x2 packed accumulation along h. NaN/density handling fused in B load.
//   grid = (6, 1, 264)
// ---------------------------------------------------------------------------
__global__ __launch_bounds__(256, 2) void u_gemm_kernel(const float* __restrict__ wt) {
    __shared__ __align__(16) float As[16][128];   // [k][x]
    __shared__ __align__(16) float Bs[16][128];   // [k][h]

    const int bc = blockIdx.z;
    const int b  = bc / CA;
    const int c  = bc % CA;
    const int x0 = blockIdx.x * 128;
    const int tid = threadIdx.x;
    const int tx = tid & 15;       // -> h quad
    const int ty = tid >> 4;       // -> x quad

    const float* w0b = g_w0 + (size_t)b * WW * XX;
    const int cin = (c == 0) ? 0 : (c - 1);
    const float* wtb = wt + ((size_t)b * CC + cin) * WW * HH;
    const bool dens = (c == 0);

    ull acc[8][4];
#pragma unroll
    for (int i = 0; i < 8; i++)
#pragma unroll
        for (int j = 0; j < 4; j++) acc[i][j] = 0ull;

    const int lr = tid >> 4;         // load row 0..15
    const int lc = (tid & 15) * 8;   // load col 0..120

    for (int k0 = 0; k0 < WW; k0 += 16) {
        // As <- w0[b][k][x0 + lc .. +7]
        {
            const float* src = w0b + (size_t)(k0 + lr) * XX + x0 + lc;
            if (x0 + lc + 7 < XX) {
                *(float4*)&As[lr][lc]     = *(const float4*)src;
                *(float4*)&As[lr][lc + 4] = *(const float4*)(src + 4);
            } else {
#pragma unroll
                for (int e = 0; e < 8; e++)
                    As[lr][lc + e] = (x0 + lc + e < XX) ? src[e] : 0.0f;
            }
        }
        // Bs <- wt_aug[b][c][k][lc .. +7]  (HH == 128 exactly)
        {
            const float* src = wtb + (size_t)(k0 + lr) * HH + lc;
            float4 v0 = *(const float4*)src;
            float4 v1 = *(const float4*)(src + 4);
            float e0[8] = {v0.x, v0.y, v0.z, v0.w, v1.x, v1.y, v1.z, v1.w};
#pragma unroll
            for (int e = 0; e < 8; e++) {
                float v = e0[e];
                v = isnan(v) ? 0.0f : (dens ? 1.0f : v);
                Bs[lr][lc + e] = v;
            }
        }
        __syncthreads();

#pragma unroll
        for (int kk = 0; kk < 16; kk++) {
            float4 a0 = *(const float4*)&As[kk][ty * 4];
            float4 a1 = *(const float4*)&As[kk][64 + ty * 4];
            ulonglong2 b0 = *(const ulonglong2*)&Bs[kk][tx * 4];
            ulonglong2 b1 = *(const ulonglong2*)&Bs[kk][64 + tx * 4];
            ull A2[8];
            A2[0] = pack2(a0.x); A2[1] = pack2(a0.y);
            A2[2] = pack2(a0.z); A2[3] = pack2(a0.w);
            A2[4] = pack2(a1.x); A2[5] = pack2(a1.y);
            A2[6] = pack2(a1.z); A2[7] = pack2(a1.w);
            ull Bp[4] = {b0.x, b0.y, b1.x, b1.y};
#pragma unroll
            for (int i = 0; i < 8; i++)
#pragma unroll
                for (int jp = 0; jp < 4; jp++)
                    fma2(acc[i][jp], A2[i], Bp[jp]);
        }
        __syncthreads();
    }

    float* Ub = g_U + (size_t)bc * XX * HH;
#pragma unroll
    for (int i = 0; i < 8; i++) {
        int x = x0 + ((i < 4) ? (ty * 4 + i) : (64 + ty * 4 + (i - 4)));
        if (x < XX) {
            float2 p0 = unpack2(acc[i][0]);
            float2 p1 = unpack2(acc[i][1]);
            float2 p2 = unpack2(acc[i][2]);
            float2 p3 = unpack2(acc[i][3]);
            *(float4*)&Ub[(size_t)x * HH + tx * 4]      = make_float4(p0.x, p0.y, p1.x, p1.y);
            *(float4*)&Ub[(size_t)x * HH + 64 + tx * 4] = make_float4(p2.x, p2.y, p3.x, p3.y);
        }
    }
}

// ---------------------------------------------------------------------------
// Kernel 3: out[b,c,x,y] = (sum_h U[b,c,x,h] * w1[b,h,y]) [/ clip(density)]
//   per block: (b, 128 x-tile, 128 y-tile); w1 strip 128x128 persistent in
//   dynamic smem; loop over 33 channels, density reciprocal kept in regs.
//   grid = (6, 3, 8), 256 threads, 8x8 micro (split halves), f32x2.
// ---------------------------------------------------------------------------
__global__ __launch_bounds__(256, 1) void out_gemm_kernel(float* __restrict__ out) {
    extern __shared__ __align__(16) float w1s[];   // [128][128]
    __shared__ __align__(16) float As3[16][128];   // [k][x]

    const int b  = blockIdx.z;
    const int x0 = blockIdx.x * 128;
    const int y0 = blockIdx.y * 128;
    const int tid = threadIdx.x;
    const int tx = tid & 15;       // -> y quad
    const int ty = tid >> 4;       // -> x quad

    // Persistent w1 strip: 128 x 128 (y zero-padded past YY)
    const float* w1b = g_w1 + (size_t)b * HH * YY;
#pragma unroll 4
    for (int p = 0; p < 64; p++) {
        int e = p * 256 + tid;
        int k = e >> 7;
        int yy = e & 127;
        int y = y0 + yy;
        w1s[k * 128 + yy] = (y < YY) ? w1b[(size_t)k * YY + y] : 0.0f;
    }
    __syncthreads();

    const int xxL = tid >> 1;          // 0..127
    const int kbL = (tid & 1) * 8;     // 0 or 8

    float rden[8][8];                  // reciprocal of clamped density

    for (int c = 0; c < CA; c++) {
        ull acc[8][4];
#pragma unroll
        for (int i = 0; i < 8; i++)
#pragma unroll
            for (int j = 0; j < 4; j++) acc[i][j] = 0ull;

        const float* Uc = g_U + ((size_t)b * CA + c) * XX * HH;

        for (int k0 = 0; k0 < HH; k0 += 16) {
            // Load As3[k][x] from U[x][k] (k contiguous in U)
            int x = x0 + xxL;
            if (x > XX - 1) x = XX - 1;   // clamp; stores are guarded
            float4 v0 = *(const float4*)&Uc[(size_t)x * HH + k0 + kbL];
            float4 v1 = *(const float4*)&Uc[(size_t)x * HH + k0 + kbL + 4];
            As3[kbL + 0][xxL] = v0.x;
            As3[kbL + 1][xxL] = v0.y;
            As3[kbL + 2][xxL] = v0.z;
            As3[kbL + 3][xxL] = v0.w;
            As3[kbL + 4][xxL] = v1.x;
            As3[kbL + 5][xxL] = v1.y;
            As3[kbL + 6][xxL] = v1.z;
            As3[kbL + 7][xxL] = v1.w;
            __syncthreads();

#pragma unroll
            for (int kk = 0; kk < 16; kk++) {
                float4 a0 = *(const float4*)&As3[kk][ty * 4];
                float4 a1 = *(const float4*)&As3[kk][64 + ty * 4];
                const float* brow = &w1s[(k0 + kk) * 128];
                ulonglong2 b0 = *(const ulonglong2*)&brow[tx * 4];
                ulonglong2 b1 = *(const ulonglong2*)&brow[64 + tx * 4];
                ull A2[8];
                A2[0] = pack2(a0.x); A2[1] = pack2(a0.y);
                A2[2] = pack2(a0.z); A2[3] = pack2(a0.w);
                A2[4] = pack2(a1.x); A2[5] = pack2(a1.y);
                A2[6] = pack2(a1.z); A2[7] = pack2(a1.w);
                ull Bp[4] = {b0.x, b0.y, b1.x, b1.y};
#pragma unroll
                for (int i = 0; i < 8; i++)
#pragma unroll
                    for (int jp = 0; jp < 4; jp++)
                        fma2(acc[i][jp], A2[i], Bp[jp]);
            }
            __syncthreads();
        }

        // Epilogue: c==0 writes density + caches reciprocal; others divide.
        float* outc = out + ((size_t)b * CA + c) * XX * YY;
#pragma unroll
        for (int i = 0; i < 8; i++) {
            int x = x0 + ((i < 4) ? (ty * 4 + i) : (64 + ty * 4 + (i - 4)));
            float2 p0 = unpack2(acc[i][0]);
            float2 p1 = unpack2(acc[i][1]);
            float2 p2 = unpack2(acc[i][2]);
            float2 p3 = unpack2(acc[i][3]);
            float vv[8] = {p0.x, p0.y, p1.x, p1.y, p2.x, p2.y, p3.x, p3.y};
#pragma unroll
            for (int jj = 0; jj < 8; jj++) {
                int y = y0 + ((jj < 4) ? (tx * 4 + jj) : (64 + tx * 4 + (jj - 4)));
                if (c == 0) {
                    float d = fminf(fmaxf(vv[jj], 1e-6f), 100000.0f);
                    rden[i][jj] = 1.0f / d;
                    if (x < XX && y < YY) outc[(size_t)x * YY + y] = vv[jj];
                } else {
                    if (x < XX && y < YY)
                        outc[(size_t)x * YY + y] = vv[jj] * rden[i][jj];
                }
            }
        }
    }
}

// ---------------------------------------------------------------------------
extern "C" void kernel_launch(void* const* d_in, const int* in_sizes, int n_in,
                              void* d_out, int out_size) {
    const float* wt      = (const float*)d_in[0];  // (8,32,256,128)
    const float* xinlon  = (const float*)d_in[1];  // (8,256)
    const float* xinlat  = (const float*)d_in[2];  // (8,128)
    const float* xoutlon = (const float*)d_in[3];  // (8,720)
    const float* xoutlat = (const float*)d_in[4];  // (8,361)
    const float* ls      = (const float*)d_in[5];  // (1,)
    float* out = (float*)d_out;                    // (8,33,720,361)

    // 1) RBF matrices
    {
        int total = BB * WW * XX + BB * HH * YY;
        int blocks = (total + 255) / 256;
        rbf_all_kernel<<<blocks, 256>>>(xinlon, xoutlon, xinlat, xoutlat, ls);
    }
    // 2) U = w0^T @ wt_aug   (contract over W)
    {
        dim3 grid((XX + 127) / 128, 1, BB * CA);   // (6, 1, 264)
        u_gemm_kernel<<<grid, 256>>>(wt);
    }
    // 3) out = U @ w1, fused density normalization (64 KB dynamic smem)
    {
        cudaFuncSetAttribute(out_gemm_kernel,
                             cudaFuncAttributeMaxDynamicSharedMemorySize,
                             128 * 128 * sizeof(float));
        dim3 grid((XX + 127) / 128, (YY + 127) / 128, BB);  // (6, 3, 8)
        out_gemm_kernel<<<grid, 256, 128 * 128 * sizeof(float)>>>(out);
    }
}

// round 13
// speedup vs baseline: 1.0018x; 1.0004x over previous
#include <cuda_runtime.h>
#include <cuda_bf16.h>
#include <math.h>

// Problem constants
#define BB 8
#define CC 32          // input channels
#define CA 33          // augmented channels (density + 32)
#define WW 256
#define HH 128
#define XX 720
#define YY 361

typedef unsigned long long ull;

// Scratch (device globals: allocation-free)
__device__ float g_w0[BB * WW * XX];              // [b][w][x]
__device__ float g_w1[BB * HH * YY];              // [b][h][y]
__device__ float g_U [(size_t)BB * CA * XX * HH]; // [b][c][x][h]

// ---------------- packed f32x2 helpers ----------------
__device__ __forceinline__ ull pack2(float v) {
    ull r;
    unsigned u = __float_as_uint(v);
    asm("mov.b64 %0, {%1, %1};" : "=l"(r) : "r"(u));
    return r;
}
__device__ __forceinline__ void fma2(ull& d, ull a, ull b) {
    asm("fma.rn.f32x2 %0, %1, %2, %0;" : "+l"(d) : "l"(a), "l"(b));
}
__device__ __forceinline__ float2 unpack2(ull v) {
    unsigned lo, hi;
    asm("mov.b64 {%0, %1}, %2;" : "=r"(lo), "=r"(hi) : "l"(v));
    return make_float2(__uint_as_float(lo), __uint_as_float(hi));
}

// ---------------------------------------------------------------------------
// Kernel 1: RBF weight matrices.  w = exp(-0.5*(xi-xo)^2 / ls^2)
// ---------------------------------------------------------------------------
__global__ void rbf_all_kernel(const float* __restrict__ inlon,
                               const float* __restrict__ outlon,
                               const float* __restrict__ inlat,
                               const float* __restrict__ outlat,
                               const float* __restrict__ ls) {
    const int N0 = BB * WW * XX;
    const int N1 = BB * HH * YY;
    int idx = blockIdx.x * blockDim.x + threadIdx.x;
    float l = ls[0];
    float inv = 0.5f / (l * l);
    if (idx < N0) {
        int m = idx % XX;
        int r = idx / XX;
        int n = r % WW;
        int b = r / WW;
        float d = inlon[b * WW + n] - outlon[b * XX + m];
        g_w0[idx] = expf(-d * d * inv);
    } else {
        int i2 = idx - N0;
        if (i2 < N1) {
            int m = i2 % YY;
            int r = i2 / YY;
            int n = r % HH;
            int b = r / HH;
            float d = inlat[b * HH + n] - outlat[b * YY + m];
            g_w1[i2] = expf(-d * d * inv);
        }
    }
}

// ---------------------------------------------------------------------------
// Kernel 2: U[b,c,x,h] = sum_w w0[b,w,x] * wt_aug[b,c,w,h]
//   per (b,c): M=720 (x), N=128 (h), K=256 (w)
//   128x128 block tile (M-padded), 256 threads, 8x8 micro (split halves),
//   f32x2 packed accumulation along h. NaN/density handling fused in B load.
//   grid = (6, 1, 264)
// ---------------------------------------------------------------------------
__global__ __launch_bounds__(256, 2) void u_gemm_kernel(const float* __restrict__ wt) {
    __shared__ __align__(16) float As[16][128];   // [k][x]
    __shared__ __align__(16) float Bs[16][128];   // [k][h]

    const int bc = blockIdx.z;
    const int b  = bc / CA;
    const int c  = bc % CA;
    const int x0 = blockIdx.x * 128;
    const int tid = threadIdx.x;
    const int tx = tid & 15;       // -> h quad
    const int ty = tid >> 4;       // -> x quad

    const float* w0b = g_w0 + (size_t)b * WW * XX;
    const int cin = (c == 0) ? 0 : (c - 1);
    const float* wtb = wt + ((size_t)b * CC + cin) * WW * HH;
    const bool dens = (c == 0);

    ull acc[8][4];
#pragma unroll
    for (int i = 0; i < 8; i++)
#pragma unroll
        for (int j = 0; j < 4; j++) acc[i][j] = 0ull;

    const int lr = tid >> 4;         // load row 0..15
    const int lc = (tid & 15) * 8;   // load col 0..120

    for (int k0 = 0; k0 < WW; k0 += 16) {
        // As <- w0[b][k][x0 + lc .. +7]
        {
            const float* src = w0b + (size_t)(k0 + lr) * XX + x0 + lc;
            if (x0 + lc + 7 < XX) {
                *(float4*)&As[lr][lc]     = *(const float4*)src;
                *(float4*)&As[lr][lc + 4] = *(const float4*)(src + 4);
            } else {
#pragma unroll
                for (int e = 0; e < 8; e++)
                    As[lr][lc + e] = (x0 + lc + e < XX) ? src[e] : 0.0f;
            }
        }
        // Bs <- wt_aug[b][c][k][lc .. +7]  (HH == 128 exactly)
        {
            const float* src = wtb + (size_t)(k0 + lr) * HH + lc;
            float4 v0 = *(const float4*)src;
            float4 v1 = *(const float4*)(src + 4);
            float e0[8] = {v0.x, v0.y, v0.z, v0.w, v1.x, v1.y, v1.z, v1.w};
#pragma unroll
            for (int e = 0; e < 8; e++) {
                float v = e0[e];
                v = isnan(v) ? 0.0f : (dens ? 1.0f : v);
                Bs[lr][lc + e] = v;
            }
        }
        __syncthreads();

#pragma unroll
        for (int kk = 0; kk < 16; kk++) {
            float4 a0 = *(const float4*)&As[kk][ty * 4];
            float4 a1 = *(const float4*)&As[kk][64 + ty * 4];
            ulonglong2 b0 = *(const ulonglong2*)&Bs[kk][tx * 4];
            ulonglong2 b1 = *(const ulonglong2*)&Bs[kk][64 + tx * 4];
            ull A2[8];
            A2[0] = pack2(a0.x); A2[1] = pack2(a0.y);
            A2[2] = pack2(a0.z); A2[3] = pack2(a0.w);
            A2[4] = pack2(a1.x); A2[5] = pack2(a1.y);
            A2[6] = pack2(a1.z); A2[7] = pack2(a1.w);
            ull Bp[4] = {b0.x, b0.y, b1.x, b1.y};
#pragma unroll
            for (int i = 0; i < 8; i++)
#pragma unroll
                for (int jp = 0; jp < 4; jp++)
                    fma2(acc[i][jp], A2[i], Bp[jp]);
        }
        __syncthreads();
    }

    float* Ub = g_U + (size_t)bc * XX * HH;
#pragma unroll
    for (int i = 0; i < 8; i++) {
        int x = x0 + ((i < 4) ? (ty * 4 + i) : (64 + ty * 4 + (i - 4)));
        if (x < XX) {
            float2 p0 = unpack2(acc[i][0]);
            float2 p1 = unpack2(acc[i][1]);
            float2 p2 = unpack2(acc[i][2]);
            float2 p3 = unpack2(acc[i][3]);
            *(float4*)&Ub[(size_t)x * HH + tx * 4]      = make_float4(p0.x, p0.y, p1.x, p1.y);
            *(float4*)&Ub[(size_t)x * HH + 64 + tx * 4] = make_float4(p2.x, p2.y, p3.x, p3.y);
        }
    }
}

// ---------------------------------------------------------------------------
// Kernel 3: out[b,c,x,y] = (sum_h U[b,c,x,h] * w1[b,h,y]) [/ clip(density)]
//   per block: (b, 128 x-tile, 128 y-tile); w1 strip 128x128 persistent in
//   dynamic smem; loop over 33 channels, density reciprocal kept in regs.
//   grid = (6, 3, 8), 256 threads, 8x8 micro (split halves), f32x2.
// ---------------------------------------------------------------------------
__global__ __launch_bounds__(256, 1) void out_gemm_kernel(float* __restrict__ out) {
    extern __shared__ __align__(16) float w1s[];   // [128][128]
    __shared__ __align__(16) float As3[16][128];   // [k][x]

    const int b  = blockIdx.z;
    const int x0 = blockIdx.x * 128;
    const int y0 = blockIdx.y * 128;
    const int tid = threadIdx.x;
    const int tx = tid & 15;       // -> y quad
    const int ty = tid >> 4;       // -> x quad

    // Persistent w1 strip: 128 x 128 (y zero-padded past YY)
    const float* w1b = g_w1 + (size_t)b * HH * YY;
#pragma unroll 4
    for (int p = 0; p < 64; p++) {
        int e = p * 256 + tid;
        int k = e >> 7;
        int yy = e & 127;
        int y = y0 + yy;
        w1s[k * 128 + yy] = (y < YY) ? w1b[(size_t)k * YY + y] : 0.0f;
    }
    __syncthreads();

    const int xxL = tid >> 1;          // 0..127
    const int kbL = (tid & 1) * 8;     // 0 or 8

    float rden[8][8];                  // reciprocal of clamped density

    for (int c = 0; c < CA; c++) {
        ull acc[8][4];
#pragma unroll
        for (int i = 0; i < 8; i++)
#pragma unroll
            for (int j = 0; j < 4; j++) acc[i][j] = 0ull;

        const float* Uc = g_U + ((size_t)b * CA + c) * XX * HH;

        for (int k0 = 0; k0 < HH; k0 += 16) {
            // Load As3[k][x] from U[x][k] (k contiguous in U)
            int x = x0 + xxL;
            if (x > XX - 1) x = XX - 1;   // clamp; stores are guarded
            float4 v0 = *(const float4*)&Uc[(size_t)x * HH + k0 + kbL];
            float4 v1 = *(const float4*)&Uc[(size_t)x * HH + k0 + kbL + 4];
            As3[kbL + 0][xxL] = v0.x;
            As3[kbL + 1][xxL] = v0.y;
            As3[kbL + 2][xxL] = v0.z;
            As3[kbL + 3][xxL] = v0.w;
            As3[kbL + 4][xxL] = v1.x;
            As3[kbL + 5][xxL] = v1.y;
            As3[kbL + 6][xxL] = v1.z;
            As3[kbL + 7][xxL] = v1.w;
            __syncthreads();

#pragma unroll
            for (int kk = 0; kk < 16; kk++) {
                float4 a0 = *(const float4*)&As3[kk][ty * 4];
                float4 a1 = *(const float4*)&As3[kk][64 + ty * 4];
                const float* brow = &w1s[(k0 + kk) * 128];
                ulonglong2 b0 = *(const ulonglong2*)&brow[tx * 4];
                ulonglong2 b1 = *(const ulonglong2*)&brow[64 + tx * 4];
                ull A2[8];
                A2[0] = pack2(a0.x); A2[1] = pack2(a0.y);
                A2[2] = pack2(a0.z); A2[3] = pack2(a0.w);
                A2[4] = pack2(a1.x); A2[5] = pack2(a1.y);
                A2[6] = pack2(a1.z); A2[7] = pack2(a1.w);
                ull Bp[4] = {b0.x, b0.y, b1.x, b1.y};
#pragma unroll
                for (int i = 0; i < 8; i++)
#pragma unroll
                    for (int jp = 0; jp < 4; jp++)
                        fma2(acc[i][jp], A2[i], Bp[jp]);
            }
            __syncthreads();
        }

        // Epilogue: c==0 writes density + caches reciprocal; others divide.
        float* outc = out + ((size_t)b * CA + c) * XX * YY;
#pragma unroll
        for (int i = 0; i < 8; i++) {
            int x = x0 + ((i < 4) ? (ty * 4 + i) : (64 + ty * 4 + (i - 4)));
            float2 p0 = unpack2(acc[i][0]);
            float2 p1 = unpack2(acc[i][1]);
            float2 p2 = unpack2(acc[i][2]);
            float2 p3 = unpack2(acc[i][3]);
            float vv[8] = {p0.x, p0.y, p1.x, p1.y, p2.x, p2.y, p3.x, p3.y};
#pragma unroll
            for (int jj = 0; jj < 8; jj++) {
                int y = y0 + ((jj < 4) ? (tx * 4 + jj) : (64 + tx * 4 + (jj - 4)));
                if (c == 0) {
                    float d = fminf(fmaxf(vv[jj], 1e-6f), 100000.0f);
                    rden[i][jj] = 1.0f / d;
                    if (x < XX && y < YY) outc[(size_t)x * YY + y] = vv[jj];
                } else {
                    if (x < XX && y < YY)
                        outc[(size_t)x * YY + y] = vv[jj] * rden[i][jj];
                }
            }
        }
    }
}

// ---------------------------------------------------------------------------
extern "C" void kernel_launch(void* const* d_in, const int* in_sizes, int n_in,
                              void* d_out, int out_size) {
    const float* wt      = (const float*)d_in[0];  // (8,32,256,128)
    const float* xinlon  = (const float*)d_in[1];  // (8,256)
    const float* xinlat  = (const float*)d_in[2];  // (8,128)
    const float* xoutlon = (const float*)d_in[3];  // (8,720)
    const float* xoutlat = (const float*)d_in[4];  // (8,361)
    const float* ls      = (const float*)d_in[5];  // (1,)
    float* out = (float*)d_out;                    // (8,33,720,361)

    // 1) RBF matrices
    {
        int total = BB * WW * XX + BB * HH * YY;
        int blocks = (total + 255) / 256;
        rbf_all_kernel<<<blocks, 256>>>(xinlon, xoutlon, xinlat, xoutlat, ls);
    }
    // 2) U = w0^T @ wt_aug   (contract over W)
    {
        dim3 grid((XX + 127) / 128, 1, BB * CA);   // (6, 1, 264)
        u_gemm_kernel<<<grid, 256>>>(wt);
    }
    // 3) out = U @ w1, fused density normalization (64 KB dynamic smem)
    {
        cudaFuncSetAttribute(out_gemm_kernel,
                             cudaFuncAttributeMaxDynamicSharedMemorySize,
                             128 * 128 * sizeof(float));
        dim3 grid((XX + 127) / 128, (YY + 127) / 128, BB);  // (6, 3, 8)
        out_gemm_kernel<<<grid, 256, 128 * 128 * sizeof(float)>>>(out);
    }
}